// round 11
// baseline (speedup 1.0000x reference)
#include <cuda_runtime.h>
#include <cuda_bf16.h>
#include <math_constants.h>
#include <cstdint>

#define N_NODES 50000
#define N_EDGES 640000
#define D 128

// ---------------- scratch ----------------
__device__ float g_h[N_NODES * D];
__device__ float g_neigh[N_NODES * D];
__device__ int   g_deg[N_NODES];          // zero-init at load; re-zeroed by scan_fused
__device__ int   g_off[N_NODES + 1];
__device__ int   g_cur[N_NODES];
__device__ int   g_srcs[N_EDGES];
__device__ float g_ws[N_EDGES];

// =========================== helpers ===================================
__device__ __forceinline__ uint32_t smem_u32(const void* p) {
    uint32_t a;
    asm("{ .reg .u64 t; cvta.to.shared.u64 t, %1; cvt.u32.u64 %0, t; }" : "=r"(a) : "l"(p));
    return a;
}
__device__ __forceinline__ void ldsm_x4(uint32_t addr, uint32_t* r) {
    asm volatile("ldmatrix.sync.aligned.m8n8.x4.shared.b16 {%0,%1,%2,%3}, [%4];"
                 : "=r"(r[0]), "=r"(r[1]), "=r"(r[2]), "=r"(r[3]) : "r"(addr));
}
__device__ __forceinline__ void mma_bf16(float* c, const uint32_t* a, uint32_t b0, uint32_t b1) {
    asm volatile(
        "mma.sync.aligned.m16n8k16.row.col.f32.bf16.bf16.f32 "
        "{%0,%1,%2,%3}, {%4,%5,%6,%7}, {%8,%9}, {%0,%1,%2,%3};"
        : "+f"(c[0]), "+f"(c[1]), "+f"(c[2]), "+f"(c[3])
        : "r"(a[0]), "r"(a[1]), "r"(a[2]), "r"(a[3]), "r"(b0), "r"(b1));
}
__device__ __forceinline__ void split2(float x, float y, uint32_t& hi, uint32_t& lo) {
    __nv_bfloat16 hx = __float2bfloat16(x), hy = __float2bfloat16(y);
    float lx = x - __bfloat162float(hx), ly = y - __bfloat162float(hy);
    __nv_bfloat162 h = __halves2bfloat162(hx, hy);
    __nv_bfloat162 l = __halves2bfloat162(__float2bfloat16(lx), __float2bfloat16(ly));
    hi = *(uint32_t*)&h;
    lo = *(uint32_t*)&l;
}
// is64 detection from any index pointer (odd words of LE int64 < 2^32 are 0)
__device__ __forceinline__ int detect_is64(const int* p) {
    int ok = 1;
    #pragma unroll
    for (int i = 1; i < 64; i += 2)
        if (p[i] != 0) { ok = 0; break; }
    return ok;
}

// ===========================================================================
// CSR build
// ===========================================================================
__global__ void hist_kernel(const void* __restrict__ dstp) {
    __shared__ int s_is64;
    if (threadIdx.x == 0) s_is64 = detect_is64((const int*)dstp);
    __syncthreads();
    int e = blockIdx.x * blockDim.x + threadIdx.x;
    if (e >= N_EDGES) return;
    int d = s_is64 ? (int)((const long long*)dstp)[e] : ((const int*)dstp)[e];
    atomicAdd(&g_deg[d], 1);
}

// Single-block fused exclusive scan over g_deg -> g_off/g_cur; zeroes g_deg.
#define SCAN_T 1024
#define SCAN_CH 49   // 49*1024 = 50176 >= 50000
__global__ void __launch_bounds__(SCAN_T, 1)
scan_fused_kernel() {
    __shared__ int sums[SCAN_T];
    const int t = threadIdx.x;
    const int beg = t * SCAN_CH;
    // pass 1: chunk sum
    int s = 0;
    for (int i = 0; i < SCAN_CH; i++) {
        int idx = beg + i;
        if (idx < N_NODES) s += g_deg[idx];
    }
    sums[t] = s;
    __syncthreads();
    // Hillis-Steele inclusive scan over 1024 partials
    for (int off = 1; off < SCAN_T; off <<= 1) {
        int x = sums[t];
        if (t >= off) x += sums[t - off];
        __syncthreads();
        sums[t] = x;
        __syncthreads();
    }
    int base = sums[t] - s;   // exclusive base for this chunk
    // pass 2: write offsets, cursors, zero deg
    int run = base;
    for (int i = 0; i < SCAN_CH; i++) {
        int idx = beg + i;
        if (idx < N_NODES) {
            int d = g_deg[idx];
            g_off[idx] = run;
            g_cur[idx] = run;
            g_deg[idx] = 0;       // clean for next replay
            run += d;
        }
    }
    if (t == 0) g_off[N_NODES] = N_EDGES;
}

__global__ void scatter_kernel(const void* __restrict__ srcp,
                               const void* __restrict__ dstp,
                               const float* __restrict__ w) {
    __shared__ int s_is64;
    if (threadIdx.x == 0) s_is64 = detect_is64((const int*)srcp);
    __syncthreads();
    int e = blockIdx.x * blockDim.x + threadIdx.x;
    if (e >= N_EDGES) return;
    int s, d;
    if (s_is64) {
        s = (int)((const long long*)srcp)[e];
        d = (int)((const long long*)dstp)[e];
    } else {
        s = ((const int*)srcp)[e];
        d = ((const int*)dstp)[e];
    }
    int pos = atomicAdd(&g_cur[d], 1);
    g_srcs[pos] = s;
    g_ws[pos]   = w[e];
}

// ---------------------------------------------------------------------------
// Gather-max: one warp per node, unroll x4 for MLP (atomic-free, order-inv.)
// ---------------------------------------------------------------------------
__global__ void gather_kernel() {
    const int node = blockIdx.x * 8 + (threadIdx.x >> 5);
    const int lane = threadIdx.x & 31;
    if (node >= N_NODES) return;
    const int beg = g_off[node], end = g_off[node + 1];

    float4 acc = make_float4(-CUDART_INF_F, -CUDART_INF_F, -CUDART_INF_F, -CUDART_INF_F);
    int e = beg;
    for (; e + 3 < end; e += 4) {
        int   s0 = g_srcs[e],     s1 = g_srcs[e + 1];
        int   s2 = g_srcs[e + 2], s3 = g_srcs[e + 3];
        float w0 = g_ws[e],     w1 = g_ws[e + 1];
        float w2 = g_ws[e + 2], w3 = g_ws[e + 3];
        float4 h0 = *(const float4*)&g_h[s0 * D + lane * 4];
        float4 h1 = *(const float4*)&g_h[s1 * D + lane * 4];
        float4 h2 = *(const float4*)&g_h[s2 * D + lane * 4];
        float4 h3 = *(const float4*)&g_h[s3 * D + lane * 4];
        acc.x = fmaxf(acc.x, h0.x * w0); acc.y = fmaxf(acc.y, h0.y * w0);
        acc.z = fmaxf(acc.z, h0.z * w0); acc.w = fmaxf(acc.w, h0.w * w0);
        acc.x = fmaxf(acc.x, h1.x * w1); acc.y = fmaxf(acc.y, h1.y * w1);
        acc.z = fmaxf(acc.z, h1.z * w1); acc.w = fmaxf(acc.w, h1.w * w1);
        acc.x = fmaxf(acc.x, h2.x * w2); acc.y = fmaxf(acc.y, h2.y * w2);
        acc.z = fmaxf(acc.z, h2.z * w2); acc.w = fmaxf(acc.w, h2.w * w2);
        acc.x = fmaxf(acc.x, h3.x * w3); acc.y = fmaxf(acc.y, h3.y * w3);
        acc.z = fmaxf(acc.z, h3.z * w3); acc.w = fmaxf(acc.w, h3.w * w3);
    }
    for (; e < end; e++) {
        int s0 = g_srcs[e]; float w0 = g_ws[e];
        float4 h0 = *(const float4*)&g_h[s0 * D + lane * 4];
        acc.x = fmaxf(acc.x, h0.x * w0); acc.y = fmaxf(acc.y, h0.y * w0);
        acc.z = fmaxf(acc.z, h0.z * w0); acc.w = fmaxf(acc.w, h0.w * w0);
    }
    if (beg == end) acc = make_float4(0.f, 0.f, 0.f, 0.f);
    *(float4*)&g_neigh[node * D + lane * 4] = acc;
}

// ===========================================================================
// Tensor-core GEMM via mma.sync (bf16 3-term split, fp32 accum) — unchanged
// ===========================================================================
#define STRIDE_A 136

__global__ void __launch_bounds__(256, 1)
gemm_mma_kernel(const float* __restrict__ feat,
                const float* __restrict__ W,
                const float* __restrict__ bias,
                float* __restrict__ out_ext,
                int mode) {
    extern __shared__ char sh[];
    const int npass = mode ? 2 : 1;
    const int K = npass * 128;
    const int strideW = K + 8;

    __nv_bfloat16* sAhi = (__nv_bfloat16*)sh;
    __nv_bfloat16* sAlo = sAhi + 128 * STRIDE_A;
    __nv_bfloat16* sWhi = sAlo + 128 * STRIDE_A;
    __nv_bfloat16* sWlo = sWhi + 128 * strideW;
    const uint32_t bAhi = smem_u32(sAhi);
    const uint32_t bAlo = smem_u32(sAlo);
    const uint32_t bWhi = smem_u32(sWhi);
    const uint32_t bWlo = smem_u32(sWlo);

    float* outp = mode ? out_ext : g_h;
    const int tid = threadIdx.x, wid = tid >> 5, lane = tid & 31;

    {
        const int K4 = K / 4;
        for (int idx = tid; idx < 128 * K4; idx += 256) {
            int r = idx / K4, k = (idx % K4) * 4;
            float4 v = *(const float4*)&W[r * K + k];
            uint32_t h0, l0, h1, l1;
            split2(v.x, v.y, h0, l0);
            split2(v.z, v.w, h1, l1);
            *(uint32_t*)&sWhi[r * strideW + k]     = h0;
            *(uint32_t*)&sWhi[r * strideW + k + 2] = h1;
            *(uint32_t*)&sWlo[r * strideW + k]     = l0;
            *(uint32_t*)&sWlo[r * strideW + k + 2] = l1;
        }
    }

    const int warp_m = wid & 3;
    const int warp_n = wid >> 2;
    const int r0 = warp_m * 32;
    const int c0 = warp_n * 64;
    const int lrow = lane & 15, lhalf = lane >> 4;
    const int qrow = lane >> 2, qcol = (lane & 3) * 2;

    float2 bias2[8];
    #pragma unroll
    for (int f = 0; f < 8; f++) {
        int c = c0 + f * 8 + qcol;
        bias2[f] = make_float2(bias[c], bias[c + 1]);
    }
    __syncthreads();

    const int numTiles = (N_NODES + 127) / 128;   // 391

    for (int tile = blockIdx.x; tile < numTiles; tile += gridDim.x) {
        const int row0 = tile * 128;
        float c[2][8][4];
        #pragma unroll
        for (int mt = 0; mt < 2; mt++)
            #pragma unroll
            for (int f = 0; f < 8; f++) {
                c[mt][f][0] = bias2[f].x; c[mt][f][1] = bias2[f].y;
                c[mt][f][2] = bias2[f].x; c[mt][f][3] = bias2[f].y;
            }

        for (int p = 0; p < npass; p++) {
            const float* srcbuf = (p == 0) ? feat : g_neigh;
            __syncthreads();
            for (int idx = tid; idx < 128 * 32; idx += 256) {
                int r = idx >> 5, k = (idx & 31) * 4;
                int row = row0 + r;
                float4 v = make_float4(0.f, 0.f, 0.f, 0.f);
                if (row < N_NODES) v = *(const float4*)&srcbuf[row * D + k];
                uint32_t h0, l0, h1, l1;
                split2(v.x, v.y, h0, l0);
                split2(v.z, v.w, h1, l1);
                *(uint32_t*)&sAhi[r * STRIDE_A + k]     = h0;
                *(uint32_t*)&sAhi[r * STRIDE_A + k + 2] = h1;
                *(uint32_t*)&sAlo[r * STRIDE_A + k]     = l0;
                *(uint32_t*)&sAlo[r * STRIDE_A + k + 2] = l1;
            }
            __syncthreads();

            const int kglob0 = p * 128;
            #pragma unroll
            for (int ks = 0; ks < 8; ks++) {
                uint32_t ah[2][4], al[2][4];
                #pragma unroll
                for (int mt = 0; mt < 2; mt++) {
                    uint32_t off = (uint32_t)(((r0 + mt * 16 + lrow) * STRIDE_A
                                    + ks * 16 + lhalf * 8) * 2);
                    ldsm_x4(bAhi + off, ah[mt]);
                    ldsm_x4(bAlo + off, al[mt]);
                }
                uint32_t wh[4][4], wl[4][4];
                #pragma unroll
                for (int g = 0; g < 4; g++) {
                    uint32_t off = (uint32_t)(((c0 + g * 16 + lrow) * strideW
                                    + kglob0 + ks * 16 + lhalf * 8) * 2);
                    ldsm_x4(bWhi + off, wh[g]);
                    ldsm_x4(bWlo + off, wl[g]);
                }
                #pragma unroll
                for (int g = 0; g < 4; g++) {
                    #pragma unroll
                    for (int mt = 0; mt < 2; mt++) {
                        mma_bf16(c[mt][2 * g],     ah[mt], wh[g][0], wh[g][2]);
                        mma_bf16(c[mt][2 * g + 1], ah[mt], wh[g][1], wh[g][3]);
                        mma_bf16(c[mt][2 * g],     al[mt], wh[g][0], wh[g][2]);
                        mma_bf16(c[mt][2 * g + 1], al[mt], wh[g][1], wh[g][3]);
                        mma_bf16(c[mt][2 * g],     ah[mt], wl[g][0], wl[g][2]);
                        mma_bf16(c[mt][2 * g + 1], ah[mt], wl[g][1], wl[g][3]);
                    }
                }
            }
        }

        #pragma unroll
        for (int mt = 0; mt < 2; mt++) {
            int r = row0 + r0 + mt * 16 + qrow;
            #pragma unroll
            for (int f = 0; f < 8; f++) {
                int cc = c0 + f * 8 + qcol;
                if (r < N_NODES)
                    *(float2*)&outp[r * 128 + cc] = make_float2(c[mt][f][0], c[mt][f][1]);
                if (r + 8 < N_NODES)
                    *(float2*)&outp[(r + 8) * 128 + cc] = make_float2(c[mt][f][2], c[mt][f][3]);
            }
        }
    }
}

// ---------------------------------------------------------------------------
extern "C" void kernel_launch(void* const* d_in, const int* in_sizes, int n_in,
                              void* d_out, int out_size) {
    const float* feat    = (const float*)d_in[0];
    const float* weight  = (const float*)d_in[1];
    const void*  src     = d_in[2];
    const void*  dst     = d_in[3];
    const float* W_pool  = (const float*)d_in[4];
    const float* b_pool  = (const float*)d_in[5];
    const float* W_neigh = (const float*)d_in[6];
    const float* b_neigh = (const float*)d_in[7];
    float* out = (float*)d_out;

    const int shmA = 2 * 128 * STRIDE_A * 2;
    const int shm1 = shmA + 2 * 128 * (128 + 8) * 2;
    const int shm2 = shmA + 2 * 128 * (256 + 8) * 2;
    static bool attr_done = false;
    if (!attr_done) {
        cudaFuncSetAttribute(gemm_mma_kernel, cudaFuncAttributeMaxDynamicSharedMemorySize, shm2);
        attr_done = true;
    }

    // persistent side stream + events (created once; never destroyed so
    // graph capture is never invalidated mid-capture)
    static cudaStream_t s1 = nullptr;
    static cudaEvent_t evFork = nullptr, evJoin = nullptr;
    if (!s1) {
        cudaStreamCreateWithFlags(&s1, cudaStreamNonBlocking);
        cudaEventCreateWithFlags(&evFork, cudaEventDisableTiming);
        cudaEventCreateWithFlags(&evJoin, cudaEventDisableTiming);
    }

    const int nbEdge = (N_EDGES + 511) / 512;

    // fork: CSR build chain on s1, GEMM1 on main stream (independent)
    cudaEventRecord(evFork, 0);
    cudaStreamWaitEvent(s1, evFork, 0);
    hist_kernel<<<nbEdge, 512, 0, s1>>>(dst);
    scan_fused_kernel<<<1, SCAN_T, 0, s1>>>();
    scatter_kernel<<<nbEdge, 512, 0, s1>>>(src, dst, weight);
    cudaEventRecord(evJoin, s1);

    gemm_mma_kernel<<<148, 256, shm1>>>(feat, W_pool, b_pool, nullptr, 0);

    // join: gather needs both g_h (GEMM1) and CSR (scatter)
    cudaStreamWaitEvent(0, evJoin, 0);
    gather_kernel<<<(N_NODES + 7) / 8, 256>>>();
    gemm_mma_kernel<<<148, 256, shm2>>>(feat, W_neigh, b_neigh, out, 1);
}

// round 12
// speedup vs baseline: 1.6857x; 1.6857x over previous
#include <cuda_runtime.h>
#include <cuda_bf16.h>
#include <math_constants.h>
#include <cstdint>

#define N_NODES 50000
#define N_EDGES 640000
#define D 128

// ---------------- scratch ----------------
__device__ float g_h[N_NODES * D];
__device__ float g_neigh[N_NODES * D];
__device__ int   g_deg[N_NODES];          // zero-init at load; re-zeroed in scan3
__device__ int   g_off[N_NODES + 1];
__device__ int   g_cur[N_NODES];
__device__ int   g_bsum[128];
__device__ int   g_boff[128];
__device__ int   g_srcs[N_EDGES];
__device__ float g_ws[N_EDGES];

// =========================== helpers ===================================
__device__ __forceinline__ uint32_t smem_u32(const void* p) {
    uint32_t a;
    asm("{ .reg .u64 t; cvta.to.shared.u64 t, %1; cvt.u32.u64 %0, t; }" : "=r"(a) : "l"(p));
    return a;
}
__device__ __forceinline__ void ldsm_x4(uint32_t addr, uint32_t* r) {
    asm volatile("ldmatrix.sync.aligned.m8n8.x4.shared.b16 {%0,%1,%2,%3}, [%4];"
                 : "=r"(r[0]), "=r"(r[1]), "=r"(r[2]), "=r"(r[3]) : "r"(addr));
}
__device__ __forceinline__ void mma_bf16(float* c, const uint32_t* a, uint32_t b0, uint32_t b1) {
    asm volatile(
        "mma.sync.aligned.m16n8k16.row.col.f32.bf16.bf16.f32 "
        "{%0,%1,%2,%3}, {%4,%5,%6,%7}, {%8,%9}, {%0,%1,%2,%3};"
        : "+f"(c[0]), "+f"(c[1]), "+f"(c[2]), "+f"(c[3])
        : "r"(a[0]), "r"(a[1]), "r"(a[2]), "r"(a[3]), "r"(b0), "r"(b1));
}
__device__ __forceinline__ void split2(float x, float y, uint32_t& hi, uint32_t& lo) {
    __nv_bfloat16 hx = __float2bfloat16(x), hy = __float2bfloat16(y);
    float lx = x - __bfloat162float(hx), ly = y - __bfloat162float(hy);
    __nv_bfloat162 h = __halves2bfloat162(hx, hy);
    __nv_bfloat162 l = __halves2bfloat162(__float2bfloat16(lx), __float2bfloat16(ly));
    hi = *(uint32_t*)&h;
    lo = *(uint32_t*)&l;
}
__device__ __forceinline__ int detect_is64(const int* p) {
    int ok = 1;
    #pragma unroll
    for (int i = 1; i < 64; i += 2)
        if (p[i] != 0) { ok = 0; break; }
    return ok;
}

// ===========================================================================
// CSR build (parallel 3-phase scan restored)
// ===========================================================================
__global__ void hist_kernel(const void* __restrict__ dstp) {
    __shared__ int s_is64;
    if (threadIdx.x == 0) s_is64 = detect_is64((const int*)dstp);
    __syncthreads();
    int e = blockIdx.x * blockDim.x + threadIdx.x;
    if (e >= N_EDGES) return;
    int d = s_is64 ? (int)((const long long*)dstp)[e] : ((const int*)dstp)[e];
    atomicAdd(&g_deg[d], 1);
}

__global__ void scan1_kernel() {
    __shared__ int tmp[512];
    int t = threadIdx.x, i = blockIdx.x * 512 + t;
    int v = (i < N_NODES) ? g_deg[i] : 0;
    tmp[t] = v;
    __syncthreads();
    for (int off = 1; off < 512; off <<= 1) {
        int x = tmp[t];
        if (t >= off) x += tmp[t - off];
        __syncthreads();
        tmp[t] = x;
        __syncthreads();
    }
    int incl = tmp[t];
    if (i < N_NODES) g_off[i] = incl - v;
    if (t == 511) g_bsum[blockIdx.x] = incl;
}
__global__ void scan2_kernel(int nb) {
    int run = 0;
    for (int b = 0; b < nb; b++) { g_boff[b] = run; run += g_bsum[b]; }
    g_off[N_NODES] = run;
}
__global__ void scan3_kernel() {
    int i = blockIdx.x * 512 + threadIdx.x;
    if (i < N_NODES) {
        int o = g_off[i] + g_boff[blockIdx.x];
        g_off[i] = o;
        g_cur[i] = o;
        g_deg[i] = 0;   // clean for next graph replay
    }
}

__global__ void scatter_kernel(const void* __restrict__ srcp,
                               const void* __restrict__ dstp,
                               const float* __restrict__ w) {
    __shared__ int s_is64;
    if (threadIdx.x == 0) s_is64 = detect_is64((const int*)srcp);
    __syncthreads();
    int e = blockIdx.x * blockDim.x + threadIdx.x;
    if (e >= N_EDGES) return;
    int s, d;
    if (s_is64) {
        s = (int)((const long long*)srcp)[e];
        d = (int)((const long long*)dstp)[e];
    } else {
        s = ((const int*)srcp)[e];
        d = ((const int*)dstp)[e];
    }
    int pos = atomicAdd(&g_cur[d], 1);
    g_srcs[pos] = s;
    g_ws[pos]   = w[e];
}

// ---------------------------------------------------------------------------
// Gather-max: one warp per node, unroll x4 for MLP (atomic-free, order-inv.)
// ---------------------------------------------------------------------------
__global__ void gather_kernel() {
    const int node = blockIdx.x * 8 + (threadIdx.x >> 5);
    const int lane = threadIdx.x & 31;
    if (node >= N_NODES) return;
    const int beg = g_off[node], end = g_off[node + 1];

    float4 acc = make_float4(-CUDART_INF_F, -CUDART_INF_F, -CUDART_INF_F, -CUDART_INF_F);
    int e = beg;
    for (; e + 3 < end; e += 4) {
        int   s0 = g_srcs[e],     s1 = g_srcs[e + 1];
        int   s2 = g_srcs[e + 2], s3 = g_srcs[e + 3];
        float w0 = g_ws[e],     w1 = g_ws[e + 1];
        float w2 = g_ws[e + 2], w3 = g_ws[e + 3];
        float4 h0 = *(const float4*)&g_h[s0 * D + lane * 4];
        float4 h1 = *(const float4*)&g_h[s1 * D + lane * 4];
        float4 h2 = *(const float4*)&g_h[s2 * D + lane * 4];
        float4 h3 = *(const float4*)&g_h[s3 * D + lane * 4];
        acc.x = fmaxf(acc.x, h0.x * w0); acc.y = fmaxf(acc.y, h0.y * w0);
        acc.z = fmaxf(acc.z, h0.z * w0); acc.w = fmaxf(acc.w, h0.w * w0);
        acc.x = fmaxf(acc.x, h1.x * w1); acc.y = fmaxf(acc.y, h1.y * w1);
        acc.z = fmaxf(acc.z, h1.z * w1); acc.w = fmaxf(acc.w, h1.w * w1);
        acc.x = fmaxf(acc.x, h2.x * w2); acc.y = fmaxf(acc.y, h2.y * w2);
        acc.z = fmaxf(acc.z, h2.z * w2); acc.w = fmaxf(acc.w, h2.w * w2);
        acc.x = fmaxf(acc.x, h3.x * w3); acc.y = fmaxf(acc.y, h3.y * w3);
        acc.z = fmaxf(acc.z, h3.z * w3); acc.w = fmaxf(acc.w, h3.w * w3);
    }
    for (; e < end; e++) {
        int s0 = g_srcs[e]; float w0 = g_ws[e];
        float4 h0 = *(const float4*)&g_h[s0 * D + lane * 4];
        acc.x = fmaxf(acc.x, h0.x * w0); acc.y = fmaxf(acc.y, h0.y * w0);
        acc.z = fmaxf(acc.z, h0.z * w0); acc.w = fmaxf(acc.w, h0.w * w0);
    }
    if (beg == end) acc = make_float4(0.f, 0.f, 0.f, 0.f);
    *(float4*)&g_neigh[node * D + lane * 4] = acc;
}

// ===========================================================================
// Tensor-core GEMM via mma.sync (bf16 3-term split, fp32 accum) — unchanged
// ===========================================================================
#define STRIDE_A 136

__global__ void __launch_bounds__(256, 1)
gemm_mma_kernel(const float* __restrict__ feat,
                const float* __restrict__ W,
                const float* __restrict__ bias,
                float* __restrict__ out_ext,
                int mode) {
    extern __shared__ char sh[];
    const int npass = mode ? 2 : 1;
    const int K = npass * 128;
    const int strideW = K + 8;

    __nv_bfloat16* sAhi = (__nv_bfloat16*)sh;
    __nv_bfloat16* sAlo = sAhi + 128 * STRIDE_A;
    __nv_bfloat16* sWhi = sAlo + 128 * STRIDE_A;
    __nv_bfloat16* sWlo = sWhi + 128 * strideW;
    const uint32_t bAhi = smem_u32(sAhi);
    const uint32_t bAlo = smem_u32(sAlo);
    const uint32_t bWhi = smem_u32(sWhi);
    const uint32_t bWlo = smem_u32(sWlo);

    float* outp = mode ? out_ext : g_h;
    const int tid = threadIdx.x, wid = tid >> 5, lane = tid & 31;

    {
        const int K4 = K / 4;
        for (int idx = tid; idx < 128 * K4; idx += 256) {
            int r = idx / K4, k = (idx % K4) * 4;
            float4 v = *(const float4*)&W[r * K + k];
            uint32_t h0, l0, h1, l1;
            split2(v.x, v.y, h0, l0);
            split2(v.z, v.w, h1, l1);
            *(uint32_t*)&sWhi[r * strideW + k]     = h0;
            *(uint32_t*)&sWhi[r * strideW + k + 2] = h1;
            *(uint32_t*)&sWlo[r * strideW + k]     = l0;
            *(uint32_t*)&sWlo[r * strideW + k + 2] = l1;
        }
    }

    const int warp_m = wid & 3;
    const int warp_n = wid >> 2;
    const int r0 = warp_m * 32;
    const int c0 = warp_n * 64;
    const int lrow = lane & 15, lhalf = lane >> 4;
    const int qrow = lane >> 2, qcol = (lane & 3) * 2;

    float2 bias2[8];
    #pragma unroll
    for (int f = 0; f < 8; f++) {
        int c = c0 + f * 8 + qcol;
        bias2[f] = make_float2(bias[c], bias[c + 1]);
    }
    __syncthreads();

    const int numTiles = (N_NODES + 127) / 128;   // 391

    for (int tile = blockIdx.x; tile < numTiles; tile += gridDim.x) {
        const int row0 = tile * 128;
        float c[2][8][4];
        #pragma unroll
        for (int mt = 0; mt < 2; mt++)
            #pragma unroll
            for (int f = 0; f < 8; f++) {
                c[mt][f][0] = bias2[f].x; c[mt][f][1] = bias2[f].y;
                c[mt][f][2] = bias2[f].x; c[mt][f][3] = bias2[f].y;
            }

        for (int p = 0; p < npass; p++) {
            const float* srcbuf = (p == 0) ? feat : g_neigh;
            __syncthreads();
            for (int idx = tid; idx < 128 * 32; idx += 256) {
                int r = idx >> 5, k = (idx & 31) * 4;
                int row = row0 + r;
                float4 v = make_float4(0.f, 0.f, 0.f, 0.f);
                if (row < N_NODES) v = *(const float4*)&srcbuf[row * D + k];
                uint32_t h0, l0, h1, l1;
                split2(v.x, v.y, h0, l0);
                split2(v.z, v.w, h1, l1);
                *(uint32_t*)&sAhi[r * STRIDE_A + k]     = h0;
                *(uint32_t*)&sAhi[r * STRIDE_A + k + 2] = h1;
                *(uint32_t*)&sAlo[r * STRIDE_A + k]     = l0;
                *(uint32_t*)&sAlo[r * STRIDE_A + k + 2] = l1;
            }
            __syncthreads();

            const int kglob0 = p * 128;
            #pragma unroll
            for (int ks = 0; ks < 8; ks++) {
                uint32_t ah[2][4], al[2][4];
                #pragma unroll
                for (int mt = 0; mt < 2; mt++) {
                    uint32_t off = (uint32_t)(((r0 + mt * 16 + lrow) * STRIDE_A
                                    + ks * 16 + lhalf * 8) * 2);
                    ldsm_x4(bAhi + off, ah[mt]);
                    ldsm_x4(bAlo + off, al[mt]);
                }
                uint32_t wh[4][4], wl[4][4];
                #pragma unroll
                for (int g = 0; g < 4; g++) {
                    uint32_t off = (uint32_t)(((c0 + g * 16 + lrow) * strideW
                                    + kglob0 + ks * 16 + lhalf * 8) * 2);
                    ldsm_x4(bWhi + off, wh[g]);
                    ldsm_x4(bWlo + off, wl[g]);
                }
                #pragma unroll
                for (int g = 0; g < 4; g++) {
                    #pragma unroll
                    for (int mt = 0; mt < 2; mt++) {
                        mma_bf16(c[mt][2 * g],     ah[mt], wh[g][0], wh[g][2]);
                        mma_bf16(c[mt][2 * g + 1], ah[mt], wh[g][1], wh[g][3]);
                        mma_bf16(c[mt][2 * g],     al[mt], wh[g][0], wh[g][2]);
                        mma_bf16(c[mt][2 * g + 1], al[mt], wh[g][1], wh[g][3]);
                        mma_bf16(c[mt][2 * g],     ah[mt], wl[g][0], wl[g][2]);
                        mma_bf16(c[mt][2 * g + 1], ah[mt], wl[g][1], wl[g][3]);
                    }
                }
            }
        }

        #pragma unroll
        for (int mt = 0; mt < 2; mt++) {
            int r = row0 + r0 + mt * 16 + qrow;
            #pragma unroll
            for (int f = 0; f < 8; f++) {
                int cc = c0 + f * 8 + qcol;
                if (r < N_NODES)
                    *(float2*)&outp[r * 128 + cc] = make_float2(c[mt][f][0], c[mt][f][1]);
                if (r + 8 < N_NODES)
                    *(float2*)&outp[(r + 8) * 128 + cc] = make_float2(c[mt][f][2], c[mt][f][3]);
            }
        }
    }
}

// ---------------------------------------------------------------------------
extern "C" void kernel_launch(void* const* d_in, const int* in_sizes, int n_in,
                              void* d_out, int out_size) {
    const float* feat    = (const float*)d_in[0];
    const float* weight  = (const float*)d_in[1];
    const void*  src     = d_in[2];
    const void*  dst     = d_in[3];
    const float* W_pool  = (const float*)d_in[4];
    const float* b_pool  = (const float*)d_in[5];
    const float* W_neigh = (const float*)d_in[6];
    const float* b_neigh = (const float*)d_in[7];
    float* out = (float*)d_out;

    const int shmA = 2 * 128 * STRIDE_A * 2;
    const int shm1 = shmA + 2 * 128 * (128 + 8) * 2;
    const int shm2 = shmA + 2 * 128 * (256 + 8) * 2;
    static bool attr_done = false;
    if (!attr_done) {
        cudaFuncSetAttribute(gemm_mma_kernel, cudaFuncAttributeMaxDynamicSharedMemorySize, shm2);
        attr_done = true;
    }

    static cudaStream_t s1 = nullptr;
    static cudaEvent_t evFork = nullptr, evJoin = nullptr;
    if (!s1) {
        cudaStreamCreateWithFlags(&s1, cudaStreamNonBlocking);
        cudaEventCreateWithFlags(&evFork, cudaEventDisableTiming);
        cudaEventCreateWithFlags(&evJoin, cudaEventDisableTiming);
    }

    const int nbEdge = (N_EDGES + 511) / 512;
    const int nbScan = (N_NODES + 511) / 512;   // 98

    // fork: CSR build chain on s1, GEMM1 on main stream (independent)
    cudaEventRecord(evFork, 0);
    cudaStreamWaitEvent(s1, evFork, 0);
    hist_kernel<<<nbEdge, 512, 0, s1>>>(dst);
    scan1_kernel<<<nbScan, 512, 0, s1>>>();
    scan2_kernel<<<1, 1, 0, s1>>>(nbScan);
    scan3_kernel<<<nbScan, 512, 0, s1>>>();
    scatter_kernel<<<nbEdge, 512, 0, s1>>>(src, dst, weight);
    cudaEventRecord(evJoin, s1);

    gemm_mma_kernel<<<148, 256, shm1>>>(feat, W_pool, b_pool, nullptr, 0);

    // join: gather needs both g_h (GEMM1) and CSR (scatter)
    cudaStreamWaitEvent(0, evJoin, 0);
    gather_kernel<<<(N_NODES + 7) / 8, 256>>>();
    gemm_mma_kernel<<<148, 256, shm2>>>(feat, W_neigh, b_neigh, out, 1);
}